// round 11
// baseline (speedup 1.0000x reference)
#include <cuda_runtime.h>
#include <cuda_bf16.h>
#include <cstdint>

// Problem constants (fixed by the reference).
#define N_TOTAL 1000000
#define N0      495616
#define N1      45056
#define N2      4096
#define E0      450560
#define E1      40960
#define D       128
#define PP      4096
#define CAP     64        // bucket capacity per dst (deg ~ Poisson(10))

// ---------------- helpers ----------------
__device__ __forceinline__ uint32_t smem_u32(const void* p) {
    uint32_t a;
    asm("{ .reg .u64 t; cvta.to.shared.u64 t, %1; cvt.u32.u64 %0, t; }" : "=r"(a) : "l"(p));
    return a;
}

__device__ __forceinline__ void ldsm_x4(uint32_t r[4], uint32_t addr) {
    asm volatile("ldmatrix.sync.aligned.m8n8.x4.shared.b16 {%0,%1,%2,%3}, [%4];"
        : "=r"(r[0]), "=r"(r[1]), "=r"(r[2]), "=r"(r[3]) : "r"(addr));
}

// D += A(16x16,row) * B(16x8,col), bf16 in, fp32 acc
__device__ __forceinline__ void mma16816(float d[4], const uint32_t a[4],
                                         uint32_t b0, uint32_t b1) {
    asm volatile("mma.sync.aligned.m16n8k16.row.col.f32.bf16.bf16.f32 "
        "{%0,%1,%2,%3}, {%4,%5,%6,%7}, {%8,%9}, {%0,%1,%2,%3};"
        : "+f"(d[0]), "+f"(d[1]), "+f"(d[2]), "+f"(d[3])
        : "r"(a[0]), "r"(a[1]), "r"(a[2]), "r"(a[3]), "r"(b0), "r"(b1));
}

__device__ __forceinline__ __nv_bfloat16 bf_hi(float v) { return __float2bfloat16(v); }
__device__ __forceinline__ __nv_bfloat16 bf_lo(float v, __nv_bfloat16 h) {
    return __float2bfloat16(v - __bfloat162float(h));
}

// ---------------- device scratch (static, no runtime allocation) ----------------
__device__ float g_h1[(size_t)N1 * D];
__device__ float g_h2[(size_t)N2 * D];

__device__ int g_deg0[N1];
__device__ int g_b0[(size_t)N1 * CAP];
__device__ int g_deg1[N2];
__device__ int g_b1[(size_t)N2 * CAP];

// ---------------- bucket CSR: one atomic pass, src pre-remapped ----------------

__global__ void k_zero() {
    int i = blockIdx.x * blockDim.x + threadIdx.x;
    if (i < N1) g_deg0[i] = 0;
    if (i < N2) g_deg1[i] = 0;
}

__global__ void k_bucket(const int* __restrict__ es0, const int* __restrict__ ed0,
                         const int* __restrict__ inodes,
                         const int* __restrict__ es1, const int* __restrict__ ed1) {
    int i = blockIdx.x * blockDim.x + threadIdx.x;
    if (i < E0) {
        int d = ed0[i];
        int p = atomicAdd(&g_deg0[d], 1);
        if (p < CAP) g_b0[d * CAP + p] = __ldg(&inodes[es0[i]]);   // remap here
    } else if (i < E0 + E1) {
        int j = i - E0;
        int d = ed1[j];
        int p = atomicAdd(&g_deg1[d], 1);
        if (p < CAP) g_b1[d * CAP + p] = es1[j];
    }
}

// ---------------- fused gather + tensor-core SAGE layer ----------------
// Per 128-row tile: stage hd (bf16 hi/lo) -> MMA vs Ws, gather+mean hn -> MMA vs Wn,
// epilogue bias(+relu). fp32 = bf16 hi+lo split: C = Ahi*Bhi + Ahi*Blo + Alo*Bhi.
// smem slabs [128 x pitch136] bf16: 0:A_hi 1:A_lo 2:Ws_hi 3:Ws_lo 4:Wn_hi 5:Wn_lo

#define PITCH   136
#define SLABE   (128 * PITCH)
#define SLAB_B  (SLABE * 2)            // 34816 B
#define SMEM_MM (6 * SLAB_B)           // 208896 B

__device__ __forceinline__ void store_row_hilo(char* smem, int r, int lane, float4 v) {
    __nv_bfloat16 hx = bf_hi(v.x), hy = bf_hi(v.y), hz = bf_hi(v.z), hw = bf_hi(v.w);
    __nv_bfloat16 lx = bf_lo(v.x, hx), ly = bf_lo(v.y, hy);
    __nv_bfloat16 lz = bf_lo(v.z, hz), lw = bf_lo(v.w, hw);
    __nv_bfloat162 h01; h01.x = hx; h01.y = hy;
    __nv_bfloat162 h23; h23.x = hz; h23.y = hw;
    __nv_bfloat162 l01; l01.x = lx; l01.y = ly;
    __nv_bfloat162 l23; l23.x = lz; l23.y = lw;
    uint2 hv; hv.x = *(uint32_t*)&h01; hv.y = *(uint32_t*)&h23;
    uint2 lv; lv.x = *(uint32_t*)&l01; lv.y = *(uint32_t*)&l23;
    size_t o = ((size_t)r * PITCH + 4 * lane) * 2;
    *(uint2*)(smem + o)          = hv;
    *(uint2*)(smem + SLAB_B + o) = lv;
}

__device__ __forceinline__ void mma_half(float acc[2][8][4], uint32_t sb, int half,
                                         int wm, int wn, int lane) {
    const uint32_t a_lrow = (uint32_t)(lane & 15);
    const uint32_t a_colq = (uint32_t)((lane >> 4) * 8);
    const uint32_t b_row  = (uint32_t)((lane & 7) + ((lane >> 4) << 3));
    const uint32_t b_col  = (uint32_t)(((lane >> 3) & 1) * 8);
    const uint32_t wHi = sb + (uint32_t)(2 + 2 * half) * SLAB_B;
    const uint32_t wLo = wHi + SLAB_B;
    #pragma unroll
    for (int kc = 0; kc < 8; kc++) {
        uint32_t aH[2][4], aL[2][4];
        #pragma unroll
        for (int mf = 0; mf < 2; mf++) {
            uint32_t arow = (uint32_t)(wm * 32 + mf * 16) + a_lrow;
            uint32_t aoff = (arow * PITCH + (uint32_t)kc * 16 + a_colq) * 2;
            ldsm_x4(aH[mf], sb + aoff);
            ldsm_x4(aL[mf], sb + SLAB_B + aoff);
        }
        #pragma unroll
        for (int nf = 0; nf < 4; nf++) {
            uint32_t nrow = (uint32_t)(wn * 64 + nf * 16) + b_row;
            uint32_t boff = (nrow * PITCH + (uint32_t)kc * 16 + b_col) * 2;
            uint32_t bH[4], bL[4];
            ldsm_x4(bH, wHi + boff);
            ldsm_x4(bL, wLo + boff);
            #pragma unroll
            for (int mf = 0; mf < 2; mf++) {
                mma16816(acc[mf][2 * nf],     aH[mf], bH[0], bH[1]);
                mma16816(acc[mf][2 * nf],     aH[mf], bL[0], bL[1]);
                mma16816(acc[mf][2 * nf],     aL[mf], bH[0], bH[1]);
                mma16816(acc[mf][2 * nf + 1], aH[mf], bH[2], bH[3]);
                mma16816(acc[mf][2 * nf + 1], aH[mf], bL[2], bL[3]);
                mma16816(acc[mf][2 * nf + 1], aL[mf], bH[2], bH[3]);
            }
        }
    }
}

template <bool RELU, bool GATHER>
__global__ void __launch_bounds__(256, 1)
k_fused(const float* __restrict__ feat, const int* __restrict__ gidx,
        const int* __restrict__ bucket, const int* __restrict__ deg,
        const float* __restrict__ Ws, const float* __restrict__ Wn,
        const float* __restrict__ bias, float* __restrict__ out, int nrows) {
    extern __shared__ char smem_raw[];
    __nv_bfloat16* slab = (__nv_bfloat16*)smem_raw;
    const uint32_t sb = smem_u32(smem_raw);
    const int tid = threadIdx.x, lane = tid & 31, wid = tid >> 5;
    const int wm = wid & 3, wn = wid >> 2;

    // stage weights once per CTA: B [n][k] hi/lo for Ws and Wn
    for (int i = tid; i < 16384; i += 256) {
        int k = i >> 7, n = i & 127;
        float w0 = __ldg(&Ws[i]);       // Ws[k][n], coalesced on n
        float w1 = __ldg(&Wn[i]);
        __nv_bfloat16 h0 = bf_hi(w0), l0 = bf_lo(w0, h0);
        __nv_bfloat16 h1 = bf_hi(w1), l1 = bf_lo(w1, h1);
        int o = n * PITCH + k;
        slab[2 * SLABE + o] = h0;
        slab[3 * SLABE + o] = l0;
        slab[4 * SLABE + o] = h1;
        slab[5 * SLABE + o] = l1;
    }

    const int r0 = wid * 16;     // this warp's 16 staging rows
    const int ntiles = nrows / 128;
    for (int tile = blockIdx.x; tile < ntiles; tile += gridDim.x) {
        const int base = tile * 128;
        float acc[2][8][4];
        #pragma unroll
        for (int mf = 0; mf < 2; mf++)
            #pragma unroll
            for (int nt = 0; nt < 8; nt++)
                #pragma unroll
                for (int q = 0; q < 4; q++) acc[mf][nt][q] = 0.f;

        __syncthreads();                 // prev tile's ldsm reads done
        // ---- half 0: hd (self features) ----
        {
            int nid_next = GATHER ? __ldg(&gidx[base + r0]) : (base + r0);
            #pragma unroll 4
            for (int rr = 0; rr < 16; rr++) {
                int nid = nid_next;
                if (rr + 1 < 16)
                    nid_next = GATHER ? __ldg(&gidx[base + r0 + rr + 1]) : (base + r0 + rr + 1);
                float4 v = __ldg(((const float4*)(feat + (size_t)nid * D)) + lane);
                store_row_hilo(smem_raw, r0 + rr, lane, v);
            }
        }
        __syncthreads();
        mma_half(acc, sb, 0, wm, wn, lane);
        __syncthreads();
        // ---- half 1: hn (neighbor mean, gathered in place) ----
        for (int rr = 0; rr < 16; rr++) {
            int row = base + r0 + rr;
            int dg = __ldg(&deg[row]);
            int n = dg < CAP ? dg : CAP;
            const int* bp = bucket + (size_t)row * CAP;
            float ax = 0.f, ay = 0.f, az = 0.f, aw = 0.f;
            int nid_next = (n > 0) ? __ldg(&bp[0]) : 0;
            for (int t = 0; t < n; t++) {
                int nid = nid_next;
                if (t + 1 < n) nid_next = __ldg(&bp[t + 1]);
                float4 v = __ldg(((const float4*)(feat + (size_t)nid * D)) + lane);
                ax += v.x; ay += v.y; az += v.z; aw += v.w;
            }
            float inv = 1.0f / fmaxf((float)dg, 1.0f);
            float4 o; o.x = ax * inv; o.y = ay * inv; o.z = az * inv; o.w = aw * inv;
            store_row_hilo(smem_raw, r0 + rr, lane, o);
        }
        __syncthreads();
        mma_half(acc, sb, 1, wm, wn, lane);

        // ---- epilogue: bias (+relu), direct global stores ----
        const int g = lane >> 2, tc = lane & 3;
        #pragma unroll
        for (int mf = 0; mf < 2; mf++) {
            int row0 = base + wm * 32 + mf * 16 + g;
            #pragma unroll
            for (int nt = 0; nt < 8; nt++) {
                int n0 = wn * 64 + nt * 8 + 2 * tc;
                float2 bv = __ldg((const float2*)(bias + n0));
                float2 v0, v1;
                v0.x = acc[mf][nt][0] + bv.x; v0.y = acc[mf][nt][1] + bv.y;
                v1.x = acc[mf][nt][2] + bv.x; v1.y = acc[mf][nt][3] + bv.y;
                if (RELU) {
                    v0.x = fmaxf(v0.x, 0.f); v0.y = fmaxf(v0.y, 0.f);
                    v1.x = fmaxf(v1.x, 0.f); v1.y = fmaxf(v1.y, 0.f);
                }
                *(float2*)(out + (size_t)row0 * D + n0)       = v0;
                *(float2*)(out + (size_t)(row0 + 8) * D + n0) = v1;
            }
        }
    }
}

// ---------------- final pos/neg gathers ----------------

__global__ void k_out(const int* __restrict__ ps, const int* __restrict__ pd,
                      const int* __restrict__ ns, const int* __restrict__ nd,
                      float* __restrict__ out) {
    int i = blockIdx.x * blockDim.x + threadIdx.x;
    if (i >= 4 * PP * 32) return;
    int q = i & 31;
    int row = i >> 5;
    int sec = row >> 12;
    int p = row & (PP - 1);
    const int* idx = (sec == 0) ? ps : (sec == 1) ? pd : (sec == 2) ? ns : nd;
    int h = __ldg(&idx[p]);
    ((float4*)out)[i] = ((const float4*)g_h2)[(size_t)h * 32 + q];
}

// ---------------- host launcher ----------------

extern "C" void kernel_launch(void* const* d_in, const int* in_sizes, int n_in,
                              void* d_out, int out_size) {
    const float* node_features = (const float*)d_in[0];
    const int*   input_nodes   = (const int*)d_in[1];
    const int*   e_src0        = (const int*)d_in[2];
    const int*   e_dst0        = (const int*)d_in[3];
    const int*   e_src1        = (const int*)d_in[4];
    const int*   e_dst1        = (const int*)d_in[5];
    const int*   pos_s         = (const int*)d_in[6];
    const int*   pos_d         = (const int*)d_in[7];
    const int*   neg_s         = (const int*)d_in[8];
    const int*   neg_d         = (const int*)d_in[9];
    const float* Ws0           = (const float*)d_in[10];
    const float* Wn0           = (const float*)d_in[11];
    const float* b0            = (const float*)d_in[12];
    const float* Ws1           = (const float*)d_in[13];
    const float* Wn1           = (const float*)d_in[14];
    const float* b1            = (const float*)d_in[15];
    float* out = (float*)d_out;

    void *p_h1, *p_h2, *p_deg0, *p_b0, *p_deg1, *p_b1;
    cudaGetSymbolAddress(&p_h1,  g_h1);
    cudaGetSymbolAddress(&p_h2,  g_h2);
    cudaGetSymbolAddress(&p_deg0, g_deg0);
    cudaGetSymbolAddress(&p_b0,  g_b0);
    cudaGetSymbolAddress(&p_deg1, g_deg1);
    cudaGetSymbolAddress(&p_b1,  g_b1);
    float* h1 = (float*)p_h1;  float* h2 = (float*)p_h2;
    int* deg0 = (int*)p_deg0;  int* b0p = (int*)p_b0;
    int* deg1 = (int*)p_deg1;  int* b1p = (int*)p_b1;

    cudaFuncSetAttribute((const void*)k_fused<true, true>,
                         cudaFuncAttributeMaxDynamicSharedMemorySize, SMEM_MM);
    cudaFuncSetAttribute((const void*)k_fused<false, false>,
                         cudaFuncAttributeMaxDynamicSharedMemorySize, SMEM_MM);

    // 1) bucket CSR: zero + single atomic pass (src remapped via input_nodes)
    k_zero<<<(N1 + 255) / 256, 256>>>();
    k_bucket<<<(E0 + E1 + 255) / 256, 256>>>(e_src0, e_dst0, input_nodes, e_src1, e_dst1);

    // 2) layer 0: fused gather + neighbor-mean + tensor-core GEMM + relu
    k_fused<true, true><<<148, 256, SMEM_MM>>>(node_features, input_nodes, b0p, deg0,
                                               Ws0, Wn0, b0, h1, N1);

    // 3) layer 1: fused (identity hd, neighbors from h1), no relu
    k_fused<false, false><<<32, 256, SMEM_MM>>>(h1, nullptr, b1p, deg1,
                                                Ws1, Wn1, b1, h2, N2);

    // 4) pos/neg output gathers
    k_out<<<(4 * PP * 32 + 255) / 256, 256>>>(pos_s, pos_d, neg_s, neg_d, out);
}

// round 12
// speedup vs baseline: 1.0060x; 1.0060x over previous
#include <cuda_runtime.h>
#include <cuda_bf16.h>
#include <cstdint>

// Problem constants (fixed by the reference).
#define N_TOTAL 1000000
#define N0      495616
#define N1      45056
#define N2      4096
#define E0      450560
#define E1      40960
#define D       128
#define PP      4096
#define CAP     64        // bucket capacity per dst (deg ~ Poisson(10))

// ---------------- helpers ----------------
__device__ __forceinline__ uint32_t smem_u32(const void* p) {
    uint32_t a;
    asm("{ .reg .u64 t; cvta.to.shared.u64 t, %1; cvt.u32.u64 %0, t; }" : "=r"(a) : "l"(p));
    return a;
}

__device__ __forceinline__ void ldsm_x4(uint32_t r[4], uint32_t addr) {
    asm volatile("ldmatrix.sync.aligned.m8n8.x4.shared.b16 {%0,%1,%2,%3}, [%4];"
        : "=r"(r[0]), "=r"(r[1]), "=r"(r[2]), "=r"(r[3]) : "r"(addr));
}

// D += A(16x16,row) * B(16x8,col), bf16 in, fp32 acc
__device__ __forceinline__ void mma16816(float d[4], const uint32_t a[4],
                                         uint32_t b0, uint32_t b1) {
    asm volatile("mma.sync.aligned.m16n8k16.row.col.f32.bf16.bf16.f32 "
        "{%0,%1,%2,%3}, {%4,%5,%6,%7}, {%8,%9}, {%0,%1,%2,%3};"
        : "+f"(d[0]), "+f"(d[1]), "+f"(d[2]), "+f"(d[3])
        : "r"(a[0]), "r"(a[1]), "r"(a[2]), "r"(a[3]), "r"(b0), "r"(b1));
}

__device__ __forceinline__ __nv_bfloat16 bf_hi(float v) { return __float2bfloat16(v); }
__device__ __forceinline__ __nv_bfloat16 bf_lo(float v, __nv_bfloat16 h) {
    return __float2bfloat16(v - __bfloat162float(h));
}

// ---------------- device scratch (static, no runtime allocation) ----------------
__device__ float g_h1[(size_t)N1 * D];
__device__ float g_h2[(size_t)N2 * D];

__device__ int g_deg0[N1];
__device__ int g_b0[(size_t)N1 * CAP];
__device__ int g_deg1[N2];
__device__ int g_b1[(size_t)N2 * CAP];

// ---------------- bucket CSR: one atomic pass, src pre-remapped ----------------

__global__ void k_zero() {
    int i = blockIdx.x * blockDim.x + threadIdx.x;
    if (i < N1) g_deg0[i] = 0;
    if (i < N2) g_deg1[i] = 0;
}

__global__ void k_bucket(const int* __restrict__ es0, const int* __restrict__ ed0,
                         const int* __restrict__ inodes,
                         const int* __restrict__ es1, const int* __restrict__ ed1) {
    int i = blockIdx.x * blockDim.x + threadIdx.x;
    if (i < E0) {
        int d = ed0[i];
        int p = atomicAdd(&g_deg0[d], 1);
        if (p < CAP) g_b0[d * CAP + p] = __ldg(&inodes[es0[i]]);   // remap here
    } else if (i < E0 + E1) {
        int j = i - E0;
        int d = ed1[j];
        int p = atomicAdd(&g_deg1[d], 1);
        if (p < CAP) g_b1[d * CAP + p] = es1[j];
    }
}

// ---------------- fused gather + tensor-core SAGE layer ----------------
// Per 128-row tile: stage hd (bf16 hi/lo) -> MMA vs Ws, gather+mean hn -> MMA vs Wn,
// epilogue bias(+relu). fp32 = bf16 hi+lo split: C = Ahi*Bhi + Ahi*Blo + Alo*Bhi.
// smem slabs [128 x pitch136] bf16: 0:A_hi 1:A_lo 2:Ws_hi 3:Ws_lo 4:Wn_hi 5:Wn_lo

#define PITCH   136
#define SLABE   (128 * PITCH)
#define SLAB_B  (SLABE * 2)            // 34816 B
#define SMEM_MM (6 * SLAB_B)           // 208896 B

__device__ __forceinline__ void store_row_hilo(char* smem, int r, int lane, float4 v) {
    __nv_bfloat16 hx = bf_hi(v.x), hy = bf_hi(v.y), hz = bf_hi(v.z), hw = bf_hi(v.w);
    __nv_bfloat16 lx = bf_lo(v.x, hx), ly = bf_lo(v.y, hy);
    __nv_bfloat16 lz = bf_lo(v.z, hz), lw = bf_lo(v.w, hw);
    __nv_bfloat162 h01; h01.x = hx; h01.y = hy;
    __nv_bfloat162 h23; h23.x = hz; h23.y = hw;
    __nv_bfloat162 l01; l01.x = lx; l01.y = ly;
    __nv_bfloat162 l23; l23.x = lz; l23.y = lw;
    uint2 hv; hv.x = *(uint32_t*)&h01; hv.y = *(uint32_t*)&h23;
    uint2 lv; lv.x = *(uint32_t*)&l01; lv.y = *(uint32_t*)&l23;
    size_t o = ((size_t)r * PITCH + 4 * lane) * 2;
    *(uint2*)(smem + o)          = hv;
    *(uint2*)(smem + SLAB_B + o) = lv;
}

__device__ __forceinline__ void mma_half(float acc[2][8][4], uint32_t sb, int half,
                                         int wm, int wn, int lane) {
    const uint32_t a_lrow = (uint32_t)(lane & 15);
    const uint32_t a_colq = (uint32_t)((lane >> 4) * 8);
    const uint32_t b_row  = (uint32_t)((lane & 7) + ((lane >> 4) << 3));
    const uint32_t b_col  = (uint32_t)(((lane >> 3) & 1) * 8);
    const uint32_t wHi = sb + (uint32_t)(2 + 2 * half) * SLAB_B;
    const uint32_t wLo = wHi + SLAB_B;
    #pragma unroll
    for (int kc = 0; kc < 8; kc++) {
        uint32_t aH[2][4], aL[2][4];
        #pragma unroll
        for (int mf = 0; mf < 2; mf++) {
            uint32_t arow = (uint32_t)(wm * 32 + mf * 16) + a_lrow;
            uint32_t aoff = (arow * PITCH + (uint32_t)kc * 16 + a_colq) * 2;
            ldsm_x4(aH[mf], sb + aoff);
            ldsm_x4(aL[mf], sb + SLAB_B + aoff);
        }
        #pragma unroll
        for (int nf = 0; nf < 4; nf++) {
            uint32_t nrow = (uint32_t)(wn * 64 + nf * 16) + b_row;
            uint32_t boff = (nrow * PITCH + (uint32_t)kc * 16 + b_col) * 2;
            uint32_t bH[4], bL[4];
            ldsm_x4(bH, wHi + boff);
            ldsm_x4(bL, wLo + boff);
            #pragma unroll
            for (int mf = 0; mf < 2; mf++) {
                mma16816(acc[mf][2 * nf],     aH[mf], bH[0], bH[1]);
                mma16816(acc[mf][2 * nf],     aH[mf], bL[0], bL[1]);
                mma16816(acc[mf][2 * nf],     aL[mf], bH[0], bH[1]);
                mma16816(acc[mf][2 * nf + 1], aH[mf], bH[2], bH[3]);
                mma16816(acc[mf][2 * nf + 1], aH[mf], bL[2], bL[3]);
                mma16816(acc[mf][2 * nf + 1], aL[mf], bH[2], bH[3]);
            }
        }
    }
}

template <bool RELU, bool GATHER>
__global__ void __launch_bounds__(256, 1)
k_fused(const float* __restrict__ feat, const int* __restrict__ gidx,
        const int* __restrict__ bucket, const int* __restrict__ deg,
        const float* __restrict__ Ws, const float* __restrict__ Wn,
        const float* __restrict__ bias, float* __restrict__ out, int nrows) {
    extern __shared__ char smem_raw[];
    __nv_bfloat16* slab = (__nv_bfloat16*)smem_raw;
    const uint32_t sb = smem_u32(smem_raw);
    const int tid = threadIdx.x, lane = tid & 31, wid = tid >> 5;
    const int wm = wid & 3, wn = wid >> 2;

    // stage weights once per CTA: B [n][k] hi/lo for Ws and Wn
    for (int i = tid; i < 16384; i += 256) {
        int k = i >> 7, n = i & 127;
        float w0 = __ldg(&Ws[i]);       // Ws[k][n], coalesced on n
        float w1 = __ldg(&Wn[i]);
        __nv_bfloat16 h0 = bf_hi(w0), l0 = bf_lo(w0, h0);
        __nv_bfloat16 h1 = bf_hi(w1), l1 = bf_lo(w1, h1);
        int o = n * PITCH + k;
        slab[2 * SLABE + o] = h0;
        slab[3 * SLABE + o] = l0;
        slab[4 * SLABE + o] = h1;
        slab[5 * SLABE + o] = l1;
    }

    const int r0 = wid * 16;     // this warp's 16 staging rows
    const int ntiles = nrows / 128;
    for (int tile = blockIdx.x; tile < ntiles; tile += gridDim.x) {
        const int base = tile * 128;
        float acc[2][8][4];
        #pragma unroll
        for (int mf = 0; mf < 2; mf++)
            #pragma unroll
            for (int nt = 0; nt < 8; nt++)
                #pragma unroll
                for (int q = 0; q < 4; q++) acc[mf][nt][q] = 0.f;

        __syncthreads();                 // prev tile's ldsm reads done
        // ---- half 0: hd (self features) ----
        {
            int nid_next = GATHER ? __ldg(&gidx[base + r0]) : (base + r0);
            #pragma unroll 4
            for (int rr = 0; rr < 16; rr++) {
                int nid = nid_next;
                if (rr + 1 < 16)
                    nid_next = GATHER ? __ldg(&gidx[base + r0 + rr + 1]) : (base + r0 + rr + 1);
                float4 v = __ldg(((const float4*)(feat + (size_t)nid * D)) + lane);
                store_row_hilo(smem_raw, r0 + rr, lane, v);
            }
        }
        __syncthreads();
        mma_half(acc, sb, 0, wm, wn, lane);
        __syncthreads();
        // ---- half 1: hn (neighbor mean, gathered in place) ----
        for (int rr = 0; rr < 16; rr++) {
            int row = base + r0 + rr;
            int dg = __ldg(&deg[row]);
            int n = dg < CAP ? dg : CAP;
            const int* bp = bucket + (size_t)row * CAP;
            float ax = 0.f, ay = 0.f, az = 0.f, aw = 0.f;
            int nid_next = (n > 0) ? __ldg(&bp[0]) : 0;
            for (int t = 0; t < n; t++) {
                int nid = nid_next;
                if (t + 1 < n) nid_next = __ldg(&bp[t + 1]);
                float4 v = __ldg(((const float4*)(feat + (size_t)nid * D)) + lane);
                ax += v.x; ay += v.y; az += v.z; aw += v.w;
            }
            float inv = 1.0f / fmaxf((float)dg, 1.0f);
            float4 o; o.x = ax * inv; o.y = ay * inv; o.z = az * inv; o.w = aw * inv;
            store_row_hilo(smem_raw, r0 + rr, lane, o);
        }
        __syncthreads();
        mma_half(acc, sb, 1, wm, wn, lane);

        // ---- epilogue: bias (+relu), direct global stores ----
        const int g = lane >> 2, tc = lane & 3;
        #pragma unroll
        for (int mf = 0; mf < 2; mf++) {
            int row0 = base + wm * 32 + mf * 16 + g;
            #pragma unroll
            for (int nt = 0; nt < 8; nt++) {
                int n0 = wn * 64 + nt * 8 + 2 * tc;
                float2 bv = __ldg((const float2*)(bias + n0));
                float2 v0, v1;
                v0.x = acc[mf][nt][0] + bv.x; v0.y = acc[mf][nt][1] + bv.y;
                v1.x = acc[mf][nt][2] + bv.x; v1.y = acc[mf][nt][3] + bv.y;
                if (RELU) {
                    v0.x = fmaxf(v0.x, 0.f); v0.y = fmaxf(v0.y, 0.f);
                    v1.x = fmaxf(v1.x, 0.f); v1.y = fmaxf(v1.y, 0.f);
                }
                *(float2*)(out + (size_t)row0 * D + n0)       = v0;
                *(float2*)(out + (size_t)(row0 + 8) * D + n0) = v1;
            }
        }
    }
}

// ---------------- final pos/neg gathers ----------------

__global__ void k_out(const int* __restrict__ ps, const int* __restrict__ pd,
                      const int* __restrict__ ns, const int* __restrict__ nd,
                      float* __restrict__ out) {
    int i = blockIdx.x * blockDim.x + threadIdx.x;
    if (i >= 4 * PP * 32) return;
    int q = i & 31;
    int row = i >> 5;
    int sec = row >> 12;
    int p = row & (PP - 1);
    const int* idx = (sec == 0) ? ps : (sec == 1) ? pd : (sec == 2) ? ns : nd;
    int h = __ldg(&idx[p]);
    ((float4*)out)[i] = ((const float4*)g_h2)[(size_t)h * 32 + q];
}

// ---------------- host launcher ----------------

extern "C" void kernel_launch(void* const* d_in, const int* in_sizes, int n_in,
                              void* d_out, int out_size) {
    const float* node_features = (const float*)d_in[0];
    const int*   input_nodes   = (const int*)d_in[1];
    const int*   e_src0        = (const int*)d_in[2];
    const int*   e_dst0        = (const int*)d_in[3];
    const int*   e_src1        = (const int*)d_in[4];
    const int*   e_dst1        = (const int*)d_in[5];
    const int*   pos_s         = (const int*)d_in[6];
    const int*   pos_d         = (const int*)d_in[7];
    const int*   neg_s         = (const int*)d_in[8];
    const int*   neg_d         = (const int*)d_in[9];
    const float* Ws0           = (const float*)d_in[10];
    const float* Wn0           = (const float*)d_in[11];
    const float* b0            = (const float*)d_in[12];
    const float* Ws1           = (const float*)d_in[13];
    const float* Wn1           = (const float*)d_in[14];
    const float* b1            = (const float*)d_in[15];
    float* out = (float*)d_out;

    void *p_h1, *p_h2, *p_deg0, *p_b0, *p_deg1, *p_b1;
    cudaGetSymbolAddress(&p_h1,  g_h1);
    cudaGetSymbolAddress(&p_h2,  g_h2);
    cudaGetSymbolAddress(&p_deg0, g_deg0);
    cudaGetSymbolAddress(&p_b0,  g_b0);
    cudaGetSymbolAddress(&p_deg1, g_deg1);
    cudaGetSymbolAddress(&p_b1,  g_b1);
    float* h1 = (float*)p_h1;  float* h2 = (float*)p_h2;
    int* deg0 = (int*)p_deg0;  int* b0p = (int*)p_b0;
    int* deg1 = (int*)p_deg1;  int* b1p = (int*)p_b1;

    cudaFuncSetAttribute((const void*)k_fused<true, true>,
                         cudaFuncAttributeMaxDynamicSharedMemorySize, SMEM_MM);
    cudaFuncSetAttribute((const void*)k_fused<false, false>,
                         cudaFuncAttributeMaxDynamicSharedMemorySize, SMEM_MM);

    // 1) bucket CSR: zero + single atomic pass (src remapped via input_nodes)
    k_zero<<<(N1 + 255) / 256, 256>>>();
    k_bucket<<<(E0 + E1 + 255) / 256, 256>>>(e_src0, e_dst0, input_nodes, e_src1, e_dst1);

    // 2) layer 0: fused gather + neighbor-mean + tensor-core GEMM + relu
    k_fused<true, true><<<148, 256, SMEM_MM>>>(node_features, input_nodes, b0p, deg0,
                                               Ws0, Wn0, b0, h1, N1);

    // 3) layer 1: fused (identity hd, neighbors from h1), no relu
    k_fused<false, false><<<32, 256, SMEM_MM>>>(h1, nullptr, b1p, deg1,
                                                Ws1, Wn1, b1, h2, N2);

    // 4) pos/neg output gathers
    k_out<<<(4 * PP * 32 + 255) / 256, 256>>>(pos_s, pos_d, neg_s, neg_d, out);
}